// round 6
// baseline (speedup 1.0000x reference)
#include <cuda_runtime.h>
#include <cuda_bf16.h>
#include <mma.h>
#include <math.h>
#include <stdint.h>

using namespace nvcuda;

// ---------------------------------------------------------------------------
// RGCN layer (no sm_103a-only instructions: harness targets plain sm_103).
//   S[d]  = sum_{e: dst=d} (h[src] + emb_rel[etype])         (edge pass)
//   main  = (norm.S) @ Wn + h @ Wl      (K-concat WMMA bf16 split GEMM)
//   gate  = sigmoid(prev @ Wsk + b)     (WMMA bf16 split GEMM)
//   out   = relu(gate*main + (1-gate)*prev)
//   deg-0 nodes (~250): recompute loop term with W_evolve in fix_kernel.
// Split precision: x = hi(bf16) + lo(bf16); products hi*hi + hi*lo + lo*hi
// with fp32 accumulate -> rel err ~2^-16.
// ---------------------------------------------------------------------------

#define D    128
#define NMAX 100000
#define LDX  136              // padded bf16 row stride for A tiles

__device__ float4 g_S4[NMAX * (D / 4)];     // 51.2 MB scratch accumulator
__device__ int    g_flag[NMAX];
__device__ int    g_list[NMAX];
__device__ int    g_cnt;
__device__ __nv_bfloat16 g_WtH[3][D * D];   // W^T hi (Wn, Wl, Wsk), [n*D+k]
__device__ __nv_bfloat16 g_WtL[3][D * D];   // W^T lo

// ---------------------------------------------------------------------------
// Edge pass: one warp per edge, lane l handles floats [4l,4l+4).
// ---------------------------------------------------------------------------
__global__ void edge_kernel(const float* __restrict__ h,
                            const float* __restrict__ emb,
                            const int* __restrict__ src,
                            const int* __restrict__ dst,
                            const int* __restrict__ et, int E) {
    int w = (blockIdx.x * blockDim.x + threadIdx.x) >> 5;
    if (w >= E) return;
    int lane = threadIdx.x & 31;
    int s = __ldg(src + w);
    int d = __ldg(dst + w);
    int r = __ldg(et + w);
    float4 hv = ((const float4*)(h + (size_t)s * D))[lane];
    float4 rv = ((const float4*)(emb + (size_t)r * D))[lane];
    float4 v = make_float4(hv.x + rv.x, hv.y + rv.y, hv.z + rv.z, hv.w + rv.w);
    float* p = (float*)&g_S4[(size_t)d * (D / 4) + lane];
    asm volatile("red.global.add.v4.f32 [%0], {%1,%2,%3,%4};"
                 :: "l"(p), "f"(v.x), "f"(v.y), "f"(v.z), "f"(v.w) : "memory");
    if (lane == 0) g_flag[d] = 1;
}

__global__ void build_list(int N) {
    int n = blockIdx.x * blockDim.x + threadIdx.x;
    if (n < N && g_flag[n] == 0) {
        int p = atomicAdd(&g_cnt, 1);
        g_list[p] = n;
    }
}

// ---------------------------------------------------------------------------
// Weight transpose + bf16 hi/lo split:  Wt[n,k] = W[k,n]
// ---------------------------------------------------------------------------
__global__ void wtrans(const float* __restrict__ Wn,
                       const float* __restrict__ Wl,
                       const float* __restrict__ Wsk) {
    int id = blockIdx.x * 256 + threadIdx.x;          // 0..49151
    if (id >= 3 * D * D) return;
    int k = id & 127, n = (id >> 7) & 127, w = id >> 14;
    const float* W = (w == 0) ? Wn : (w == 1) ? Wl : Wsk;
    float x = W[k * D + n];
    __nv_bfloat16 hi = __float2bfloat16(x);
    float r = x - __bfloat162float(hi);
    g_WtH[w][n * D + k] = hi;
    g_WtL[w][n * D + k] = __float2bfloat16(r);
}

// ---------------------------------------------------------------------------
// Node pass: WMMA bf16, per block M=128 nodes x N=128 outputs.
// SMEM: [sXhi 34816][sXlo 34816][sG 64KB][sP2 64KB] = 196 KB.
// 8 warps tiled 4(M) x 2(N): warp owns 32 rows x 64 cols = 2x4 acc frags.
// ---------------------------------------------------------------------------
#define OFF_XHI 0
#define OFF_XLO 34816
#define OFF_G   69632
#define OFF_P2  135168
#define SM_TOT  200704

typedef wmma::fragment<wmma::matrix_a, 16, 16, 16, __nv_bfloat16, wmma::row_major> FragA;
typedef wmma::fragment<wmma::matrix_b, 16, 16, 16, __nv_bfloat16, wmma::col_major> FragB;
typedef wmma::fragment<wmma::accumulator, 16, 16, 16, float> FragC;

__device__ __forceinline__ void stage_X(char* sm, const float* __restrict__ X,
                                        const float* __restrict__ rowscale,
                                        int node0, int N, int tid) {
    __nv_bfloat16* sHi = (__nv_bfloat16*)(sm + OFF_XHI);
    __nv_bfloat16* sLo = (__nv_bfloat16*)(sm + OFF_XLO);
    #pragma unroll 4
    for (int i = tid; i < 128 * 32; i += 256) {
        int row = i >> 5, c4 = i & 31;
        float4 v = make_float4(0.f, 0.f, 0.f, 0.f);
        int gr = node0 + row;
        float sc = 1.f;
        if (gr < N) {
            v = ((const float4*)(X + (size_t)gr * D))[c4];
            if (rowscale) sc = __ldg(rowscale + gr);
        }
        float x0 = v.x * sc, x1 = v.y * sc, x2 = v.z * sc, x3 = v.w * sc;
        __nv_bfloat16 h0 = __float2bfloat16(x0), h1 = __float2bfloat16(x1);
        __nv_bfloat16 h2 = __float2bfloat16(x2), h3 = __float2bfloat16(x3);
        __nv_bfloat162 H01; H01.x = h0; H01.y = h1;
        __nv_bfloat162 H23; H23.x = h2; H23.y = h3;
        __nv_bfloat162 L01, L23;
        L01.x = __float2bfloat16(x0 - __bfloat162float(h0));
        L01.y = __float2bfloat16(x1 - __bfloat162float(h1));
        L23.x = __float2bfloat16(x2 - __bfloat162float(h2));
        L23.y = __float2bfloat16(x3 - __bfloat162float(h3));
        int off = row * LDX + c4 * 4;
        *(__nv_bfloat162*)(sHi + off)     = H01;
        *(__nv_bfloat162*)(sHi + off + 2) = H23;
        *(__nv_bfloat162*)(sLo + off)     = L01;
        *(__nv_bfloat162*)(sLo + off + 2) = L23;
    }
}

__device__ __forceinline__ void gemm3(char* sm, FragC acc[2][4],
                                      const __nv_bfloat16* __restrict__ WH,
                                      const __nv_bfloat16* __restrict__ WL,
                                      int warp_m, int warp_n) {
    const __nv_bfloat16* sHi = (const __nv_bfloat16*)(sm + OFF_XHI);
    const __nv_bfloat16* sLo = (const __nv_bfloat16*)(sm + OFF_XLO);
    #pragma unroll 1
    for (int prod = 0; prod < 3; prod++) {
        const __nv_bfloat16* A = (prod == 2) ? sLo : sHi;
        const __nv_bfloat16* B = (prod == 1) ? WL : WH;
        #pragma unroll 1
        for (int k = 0; k < 8; k++) {
            FragA fa[2];
            #pragma unroll
            for (int i = 0; i < 2; i++)
                wmma::load_matrix_sync(fa[i],
                    A + (warp_m * 32 + i * 16) * LDX + k * 16, LDX);
            FragB fb[4];
            #pragma unroll
            for (int j = 0; j < 4; j++)
                wmma::load_matrix_sync(fb[j],
                    B + (warp_n * 64 + j * 16) * D + k * 16, D);
            #pragma unroll
            for (int i = 0; i < 2; i++)
                #pragma unroll
                for (int j = 0; j < 4; j++)
                    wmma::mma_sync(acc[i][j], fa[i], fb[j], acc[i][j]);
        }
    }
}

__global__ void __launch_bounds__(256)
node_wmma(const float* __restrict__ h, const float* __restrict__ prev,
          const float* __restrict__ norm, const float* __restrict__ bias,
          float* __restrict__ out, int N) {
    extern __shared__ char sm[];
    float* sG  = (float*)(sm + OFF_G);
    float* sP2 = (float*)(sm + OFF_P2);
    int tid = threadIdx.x;
    int wid = tid >> 5;
    int warp_m = wid & 3, warp_n = wid >> 2;
    int node0 = blockIdx.x * 128;
    FragC acc[2][4];

    // ---- Phase 1: skip = prev @ Wsk ; g = sigmoid(skip+b); P2=(1-g)*prev ----
    stage_X(sm, prev, nullptr, node0, N, tid);
    __syncthreads();
    #pragma unroll
    for (int i = 0; i < 2; i++)
        #pragma unroll
        for (int j = 0; j < 4; j++) wmma::fill_fragment(acc[i][j], 0.f);
    gemm3(sm, acc, g_WtH[2], g_WtL[2], warp_m, warp_n);
    #pragma unroll
    for (int i = 0; i < 2; i++)
        #pragma unroll
        for (int j = 0; j < 4; j++)
            wmma::store_matrix_sync(
                sG + (warp_m * 32 + i * 16) * D + warp_n * 64 + j * 16,
                acc[i][j], D, wmma::mem_row_major);
    __syncthreads();
    {
        const __nv_bfloat16* sHi = (const __nv_bfloat16*)(sm + OFF_XHI);
        const __nv_bfloat16* sLo = (const __nv_bfloat16*)(sm + OFF_XLO);
        #pragma unroll 4
        for (int i = tid; i < 128 * 32; i += 256) {
            int m = i >> 5, c4 = i & 31;
            float4 z = ((float4*)sG)[m * 32 + c4];
            int off = m * LDX + c4 * 4;
            __nv_bfloat162 H01 = *(const __nv_bfloat162*)(sHi + off);
            __nv_bfloat162 H23 = *(const __nv_bfloat162*)(sHi + off + 2);
            __nv_bfloat162 L01 = *(const __nv_bfloat162*)(sLo + off);
            __nv_bfloat162 L23 = *(const __nv_bfloat162*)(sLo + off + 2);
            float p0 = __bfloat162float(H01.x) + __bfloat162float(L01.x);
            float p1 = __bfloat162float(H01.y) + __bfloat162float(L01.y);
            float p2 = __bfloat162float(H23.x) + __bfloat162float(L23.x);
            float p3 = __bfloat162float(H23.y) + __bfloat162float(L23.y);
            float4 bz = ((const float4*)bias)[c4];
            float4 g4;
            g4.x = 1.f / (1.f + __expf(-(z.x + bz.x)));
            g4.y = 1.f / (1.f + __expf(-(z.y + bz.y)));
            g4.z = 1.f / (1.f + __expf(-(z.z + bz.z)));
            g4.w = 1.f / (1.f + __expf(-(z.w + bz.w)));
            ((float4*)sG)[m * 32 + c4] = g4;
            ((float4*)sP2)[m * 32 + c4] =
                make_float4((1.f - g4.x) * p0, (1.f - g4.y) * p1,
                            (1.f - g4.z) * p2, (1.f - g4.w) * p3);
        }
    }
    __syncthreads();

    // ---- Phase 2: main = (norm.S) @ Wn + h @ Wl  (K-concat accumulate) ----
    #pragma unroll
    for (int i = 0; i < 2; i++)
        #pragma unroll
        for (int j = 0; j < 4; j++) wmma::fill_fragment(acc[i][j], 0.f);
    stage_X(sm, (const float*)g_S4, norm, node0, N, tid);
    __syncthreads();
    gemm3(sm, acc, g_WtH[0], g_WtL[0], warp_m, warp_n);
    __syncthreads();                       // all warps done reading S tile
    stage_X(sm, h, nullptr, node0, N, tid);
    __syncthreads();
    gemm3(sm, acc, g_WtH[1], g_WtL[1], warp_m, warp_n);
    __syncthreads();                       // done reading before scratch reuse

    // ---- Final epilogue: out = relu(g*main + P2), scratch aliases X tiles --
    float* sF = (float*)(sm + OFF_XHI);    // 64 KB scratch in X region
    #pragma unroll
    for (int i = 0; i < 2; i++)
        #pragma unroll
        for (int j = 0; j < 4; j++)
            wmma::store_matrix_sync(
                sF + (warp_m * 32 + i * 16) * D + warp_n * 64 + j * 16,
                acc[i][j], D, wmma::mem_row_major);
    __syncthreads();
    #pragma unroll 4
    for (int i = tid; i < 128 * 32; i += 256) {
        int m = i >> 5, c4 = i & 31;
        if (node0 + m >= N) continue;
        float4 r  = ((float4*)sF)[m * 32 + c4];
        float4 g4 = ((float4*)sG)[m * 32 + c4];
        float4 p2 = ((float4*)sP2)[m * 32 + c4];
        float4 o;
        o.x = fmaxf(fmaf(g4.x, r.x, p2.x), 0.f);
        o.y = fmaxf(fmaf(g4.y, r.y, p2.y), 0.f);
        o.z = fmaxf(fmaf(g4.z, r.z, p2.z), 0.f);
        o.w = fmaxf(fmaf(g4.w, r.w, p2.w), 0.f);
        ((float4*)(out + (size_t)(node0 + m) * D))[c4] = o;
    }
}

// ---------------------------------------------------------------------------
// Fix-up for degree-0 nodes (agg==0): out = relu(g*(h@We) + (1-g)*prev)
// ---------------------------------------------------------------------------
__global__ void fix_kernel(const float* __restrict__ h,
                           const float* __restrict__ prev,
                           const float* __restrict__ We,
                           const float* __restrict__ Wsk,
                           const float* __restrict__ bias,
                           float* __restrict__ out) {
    __shared__ float sh[D], sp[D];
    int t = threadIdx.x;
    int cnt = g_cnt;
    for (int ii = blockIdx.x; ii < cnt; ii += gridDim.x) {
        int node = g_list[ii];
        __syncthreads();
        sh[t] = h[(size_t)node * D + t];
        sp[t] = prev[(size_t)node * D + t];
        __syncthreads();
        float lp = 0.f, sk = 0.f;
        #pragma unroll 8
        for (int k = 0; k < D; k++) {
            lp = fmaf(sh[k], __ldg(We  + k * D + t), lp);
            sk = fmaf(sp[k], __ldg(Wsk + k * D + t), sk);
        }
        float g = 1.f / (1.f + __expf(-(sk + bias[t])));
        out[(size_t)node * D + t] = fmaxf(g * lp + (1.f - g) * sp[t], 0.f);
    }
}

// ---------------------------------------------------------------------------
extern "C" void kernel_launch(void* const* d_in, const int* in_sizes, int n_in,
                              void* d_out, int out_size) {
    const float* h    = (const float*)d_in[0];
    const float* prev = (const float*)d_in[1];
    const float* emb  = (const float*)d_in[2];
    const float* norm = (const float*)d_in[3];
    const float* Wn   = (const float*)d_in[4];
    const float* Wl   = (const float*)d_in[5];
    const float* We   = (const float*)d_in[6];
    const float* Wsk  = (const float*)d_in[7];
    const float* bias = (const float*)d_in[8];
    const int* src = (const int*)d_in[9];     // int32 (JAX x64-disabled)
    const int* dst = (const int*)d_in[10];
    const int* et  = (const int*)d_in[11];
    int N = in_sizes[3];
    if (N > NMAX) N = NMAX;
    int E = in_sizes[9];
    float* out = (float*)d_out;

    void *pS, *pF, *pC;
    cudaGetSymbolAddress(&pS, g_S4);
    cudaGetSymbolAddress(&pF, g_flag);
    cudaGetSymbolAddress(&pC, g_cnt);
    cudaMemsetAsync(pS, 0, (size_t)N * D * sizeof(float), 0);
    cudaMemsetAsync(pF, 0, (size_t)N * sizeof(int), 0);
    cudaMemsetAsync(pC, 0, sizeof(int), 0);

    wtrans<<<192, 256>>>(Wn, Wl, Wsk);

    int edgeBlocks = (E + 7) / 8;
    edge_kernel<<<edgeBlocks, 256>>>(h, emb, src, dst, et, E);

    build_list<<<(N + 255) / 256, 256>>>(N);

    cudaFuncSetAttribute(node_wmma,
                         cudaFuncAttributeMaxDynamicSharedMemorySize, SM_TOT);
    node_wmma<<<(N + 127) / 128, 256, SM_TOT>>>(h, prev, norm, bias, out, N);

    fix_kernel<<<2048, 128>>>(h, prev, We, Wsk, bias, out);
}

// round 7
// speedup vs baseline: 1.4818x; 1.4818x over previous
#include <cuda_runtime.h>
#include <cuda_bf16.h>
#include <mma.h>
#include <math.h>
#include <stdint.h>

using namespace nvcuda;

// ---------------------------------------------------------------------------
// RGCN layer (plain sm_103 target: WMMA bf16, no tcgen05).
//   S[d]  = sum_{e: dst=d} (h[src] + emb_rel[etype])         (edge pass)
//   gate  = sigmoid(prev @ Wsk + b)          -> g_G scratch   (GEMM phase 1)
//   main  = (norm.S) @ Wn + h @ Wl           (K-concat accumulate, phases 2-3)
//   out   = relu(gate*main + (1-gate)*prev)
//   deg-0 nodes (~250): recompute loop term with W_evolve in fix_kernel.
// Split precision: x = hi(bf16) + lo(bf16); hi*hi + hi*lo + lo*hi, fp32 acc.
// A and B tiles both staged in SMEM so load_matrix_sync emits LDSM (the R6
// global-B path lowered to scalar LDG.U16 and was L1-bound at 59.8%).
// ---------------------------------------------------------------------------

#define D    128
#define NMAX 100000
#define LDA  136
#define LDB  136

__device__ float4 g_S4[NMAX * (D / 4)];     // 51.2 MB scatter accumulator
__device__ float  g_G[NMAX * D];            // 51.2 MB gate scratch
__device__ int    g_flag[NMAX];
__device__ int    g_list[NMAX];
__device__ int    g_cnt;
__device__ __nv_bfloat16 g_WtH[3][D * D];   // W^T hi (Wn, Wl, Wsk), [n*D+k]
__device__ __nv_bfloat16 g_WtL[3][D * D];   // W^T lo

// ---------------------------------------------------------------------------
// Edge pass: one warp per edge, lane l handles floats [4l,4l+4).
// ---------------------------------------------------------------------------
__global__ void edge_kernel(const float* __restrict__ h,
                            const float* __restrict__ emb,
                            const int* __restrict__ src,
                            const int* __restrict__ dst,
                            const int* __restrict__ et, int E) {
    int w = (blockIdx.x * blockDim.x + threadIdx.x) >> 5;
    if (w >= E) return;
    int lane = threadIdx.x & 31;
    int s = __ldg(src + w);
    int d = __ldg(dst + w);
    int r = __ldg(et + w);
    float4 hv = ((const float4*)(h + (size_t)s * D))[lane];
    float4 rv = ((const float4*)(emb + (size_t)r * D))[lane];
    float4 v = make_float4(hv.x + rv.x, hv.y + rv.y, hv.z + rv.z, hv.w + rv.w);
    float* p = (float*)&g_S4[(size_t)d * (D / 4) + lane];
    asm volatile("red.global.add.v4.f32 [%0], {%1,%2,%3,%4};"
                 :: "l"(p), "f"(v.x), "f"(v.y), "f"(v.z), "f"(v.w) : "memory");
    if (lane == 0) g_flag[d] = 1;
}

__global__ void build_list(int N) {
    int n = blockIdx.x * blockDim.x + threadIdx.x;
    if (n < N && g_flag[n] == 0) {
        int p = atomicAdd(&g_cnt, 1);
        g_list[p] = n;
    }
}

// ---------------------------------------------------------------------------
// Weight transpose + bf16 hi/lo split:  Wt[n,k] = W[k,n]
// ---------------------------------------------------------------------------
__global__ void wtrans(const float* __restrict__ Wn,
                       const float* __restrict__ Wl,
                       const float* __restrict__ Wsk) {
    int id = blockIdx.x * 256 + threadIdx.x;          // 0..49151
    if (id >= 3 * D * D) return;
    int k = id & 127, n = (id >> 7) & 127, w = id >> 14;
    const float* W = (w == 0) ? Wn : (w == 1) ? Wl : Wsk;
    float x = W[k * D + n];
    __nv_bfloat16 hi = __float2bfloat16(x);
    float r = x - __bfloat162float(hi);
    g_WtH[w][n * D + k] = hi;
    g_WtL[w][n * D + k] = __float2bfloat16(r);
}

// ---------------------------------------------------------------------------
// Node pass: per block M=128 nodes x N=128 outputs, 512 threads = 16 warps
// tiled 4(M) x 4(N); warp tile 32x32 = 2x2 fp32 acc frags.
// SMEM: A hi/lo (2x34816) + B hi/lo (2x34816) = 139264 B.
// ---------------------------------------------------------------------------
#define OFF_AHI 0
#define OFF_ALO 34816
#define OFF_BHI 69632
#define OFF_BLO 104448
#define SM_TOT  139264

typedef wmma::fragment<wmma::matrix_a, 16, 16, 16, __nv_bfloat16, wmma::row_major> FragA;
typedef wmma::fragment<wmma::matrix_b, 16, 16, 16, __nv_bfloat16, wmma::col_major> FragB;
typedef wmma::fragment<wmma::accumulator, 16, 16, 16, float> FragC;

__device__ __forceinline__ void stage_X(char* sm, const float* __restrict__ X,
                                        const float* __restrict__ rowscale,
                                        int node0, int N, int tid) {
    __nv_bfloat16* sHi = (__nv_bfloat16*)(sm + OFF_AHI);
    __nv_bfloat16* sLo = (__nv_bfloat16*)(sm + OFF_ALO);
    #pragma unroll 2
    for (int i = tid; i < 128 * 32; i += 512) {
        int row = i >> 5, c4 = i & 31;
        float4 v = make_float4(0.f, 0.f, 0.f, 0.f);
        int gr = node0 + row;
        float sc = 1.f;
        if (gr < N) {
            v = ((const float4*)(X + (size_t)gr * D))[c4];
            if (rowscale) sc = __ldg(rowscale + gr);
        }
        float x0 = v.x * sc, x1 = v.y * sc, x2 = v.z * sc, x3 = v.w * sc;
        __nv_bfloat16 h0 = __float2bfloat16(x0), h1 = __float2bfloat16(x1);
        __nv_bfloat16 h2 = __float2bfloat16(x2), h3 = __float2bfloat16(x3);
        __nv_bfloat162 H01; H01.x = h0; H01.y = h1;
        __nv_bfloat162 H23; H23.x = h2; H23.y = h3;
        __nv_bfloat162 L01, L23;
        L01.x = __float2bfloat16(x0 - __bfloat162float(h0));
        L01.y = __float2bfloat16(x1 - __bfloat162float(h1));
        L23.x = __float2bfloat16(x2 - __bfloat162float(h2));
        L23.y = __float2bfloat16(x3 - __bfloat162float(h3));
        int off = row * LDA + c4 * 4;
        *(__nv_bfloat162*)(sHi + off)     = H01;
        *(__nv_bfloat162*)(sHi + off + 2) = H23;
        *(__nv_bfloat162*)(sLo + off)     = L01;
        *(__nv_bfloat162*)(sLo + off + 2) = L23;
    }
}

__device__ __forceinline__ void stage_B(char* sm,
                                        const __nv_bfloat16* __restrict__ WH,
                                        const __nv_bfloat16* __restrict__ WL,
                                        int tid) {
    __nv_bfloat16* sBH = (__nv_bfloat16*)(sm + OFF_BHI);
    __nv_bfloat16* sBL = (__nv_bfloat16*)(sm + OFF_BLO);
    #pragma unroll 2
    for (int i = tid; i < 128 * 16; i += 512) {   // uint4 = 8 bf16
        int n = i >> 4, kq = i & 15;
        *(uint4*)(sBH + n * LDB + kq * 8) = *(const uint4*)(WH + n * D + kq * 8);
        *(uint4*)(sBL + n * LDB + kq * 8) = *(const uint4*)(WL + n * D + kq * 8);
    }
}

__device__ __forceinline__ void gemm3(char* sm, FragC acc[2][2],
                                      int warp_m, int warp_n) {
    const __nv_bfloat16* sAHi = (const __nv_bfloat16*)(sm + OFF_AHI);
    const __nv_bfloat16* sALo = (const __nv_bfloat16*)(sm + OFF_ALO);
    const __nv_bfloat16* sBHi = (const __nv_bfloat16*)(sm + OFF_BHI);
    const __nv_bfloat16* sBLo = (const __nv_bfloat16*)(sm + OFF_BLO);
    #pragma unroll 1
    for (int prod = 0; prod < 3; prod++) {
        const __nv_bfloat16* A = (prod == 2) ? sALo : sAHi;
        const __nv_bfloat16* B = (prod == 1) ? sBLo : sBHi;
        #pragma unroll 1
        for (int k = 0; k < 8; k++) {
            FragA fa[2];
            #pragma unroll
            for (int i = 0; i < 2; i++)
                wmma::load_matrix_sync(fa[i],
                    A + (warp_m * 32 + i * 16) * LDA + k * 16, LDA);
            FragB fb[2];
            #pragma unroll
            for (int j = 0; j < 2; j++)
                wmma::load_matrix_sync(fb[j],
                    B + (warp_n * 32 + j * 16) * LDB + k * 16, LDB);
            #pragma unroll
            for (int i = 0; i < 2; i++)
                #pragma unroll
                for (int j = 0; j < 2; j++)
                    wmma::mma_sync(acc[i][j], fa[i], fb[j], acc[i][j]);
        }
    }
}

__global__ void __launch_bounds__(512)
node_wmma(const float* __restrict__ h, const float* __restrict__ prev,
          const float* __restrict__ norm, const float* __restrict__ bias,
          float* __restrict__ out, int N) {
    extern __shared__ char sm[];
    float* sF = (float*)(sm + OFF_AHI);    // 64 KB fp32 scratch aliases A tiles
    int tid = threadIdx.x;
    int wid = tid >> 5;
    int warp_m = wid & 3, warp_n = wid >> 2;
    int node0 = blockIdx.x * 128;
    FragC acc[2][2];

    // ---- Phase 1: skip = prev @ Wsk ; g = sigmoid(skip+b) -> g_G ----
    stage_X(sm, prev, nullptr, node0, N, tid);
    stage_B(sm, g_WtH[2], g_WtL[2], tid);
    __syncthreads();
    #pragma unroll
    for (int i = 0; i < 2; i++)
        #pragma unroll
        for (int j = 0; j < 2; j++) wmma::fill_fragment(acc[i][j], 0.f);
    gemm3(sm, acc, warp_m, warp_n);
    __syncthreads();                       // A reads done; alias as sF
    #pragma unroll
    for (int i = 0; i < 2; i++)
        #pragma unroll
        for (int j = 0; j < 2; j++)
            wmma::store_matrix_sync(
                sF + (warp_m * 32 + i * 16) * D + warp_n * 32 + j * 16,
                acc[i][j], D, wmma::mem_row_major);
    __syncthreads();
    #pragma unroll 2
    for (int i = tid; i < 128 * 32; i += 512) {
        int m = i >> 5, c4 = i & 31;
        if (node0 + m >= N) continue;
        float4 z  = ((float4*)sF)[m * 32 + c4];
        float4 bz = ((const float4*)bias)[c4];
        float4 g4;
        g4.x = 1.f / (1.f + __expf(-(z.x + bz.x)));
        g4.y = 1.f / (1.f + __expf(-(z.y + bz.y)));
        g4.z = 1.f / (1.f + __expf(-(z.z + bz.z)));
        g4.w = 1.f / (1.f + __expf(-(z.w + bz.w)));
        ((float4*)(g_G + (size_t)(node0 + m) * D))[c4] = g4;
    }
    __syncthreads();

    // ---- Phase 2+3: main = (norm.S) @ Wn + h @ Wl (K-concat accumulate) ----
    #pragma unroll
    for (int i = 0; i < 2; i++)
        #pragma unroll
        for (int j = 0; j < 2; j++) wmma::fill_fragment(acc[i][j], 0.f);
    stage_X(sm, (const float*)g_S4, norm, node0, N, tid);
    stage_B(sm, g_WtH[0], g_WtL[0], tid);
    __syncthreads();
    gemm3(sm, acc, warp_m, warp_n);
    __syncthreads();
    stage_X(sm, h, nullptr, node0, N, tid);
    stage_B(sm, g_WtH[1], g_WtL[1], tid);
    __syncthreads();
    gemm3(sm, acc, warp_m, warp_n);
    __syncthreads();

    // ---- Final epilogue: out = relu(g*main + (1-g)*prev) ----
    #pragma unroll
    for (int i = 0; i < 2; i++)
        #pragma unroll
        for (int j = 0; j < 2; j++)
            wmma::store_matrix_sync(
                sF + (warp_m * 32 + i * 16) * D + warp_n * 32 + j * 16,
                acc[i][j], D, wmma::mem_row_major);
    __syncthreads();
    #pragma unroll 2
    for (int i = tid; i < 128 * 32; i += 512) {
        int m = i >> 5, c4 = i & 31;
        if (node0 + m >= N) continue;
        float4 r  = ((float4*)sF)[m * 32 + c4];
        float4 g4 = ((const float4*)(g_G + (size_t)(node0 + m) * D))[c4];
        float4 pv = ((const float4*)(prev + (size_t)(node0 + m) * D))[c4];
        float4 o;
        o.x = fmaxf(g4.x * r.x + (1.f - g4.x) * pv.x, 0.f);
        o.y = fmaxf(g4.y * r.y + (1.f - g4.y) * pv.y, 0.f);
        o.z = fmaxf(g4.z * r.z + (1.f - g4.z) * pv.z, 0.f);
        o.w = fmaxf(g4.w * r.w + (1.f - g4.w) * pv.w, 0.f);
        ((float4*)(out + (size_t)(node0 + m) * D))[c4] = o;
    }
}

// ---------------------------------------------------------------------------
// Fix-up for degree-0 nodes (agg==0): out = relu(g*(h@We) + (1-g)*prev)
// ---------------------------------------------------------------------------
__global__ void fix_kernel(const float* __restrict__ h,
                           const float* __restrict__ prev,
                           const float* __restrict__ We,
                           const float* __restrict__ Wsk,
                           const float* __restrict__ bias,
                           float* __restrict__ out) {
    __shared__ float sh[D], sp[D];
    int t = threadIdx.x;
    int cnt = g_cnt;
    for (int ii = blockIdx.x; ii < cnt; ii += gridDim.x) {
        int node = g_list[ii];
        __syncthreads();
        sh[t] = h[(size_t)node * D + t];
        sp[t] = prev[(size_t)node * D + t];
        __syncthreads();
        float lp = 0.f, sk = 0.f;
        #pragma unroll 8
        for (int k = 0; k < D; k++) {
            lp = fmaf(sh[k], __ldg(We  + k * D + t), lp);
            sk = fmaf(sp[k], __ldg(Wsk + k * D + t), sk);
        }
        float g = 1.f / (1.f + __expf(-(sk + bias[t])));
        out[(size_t)node * D + t] = fmaxf(g * lp + (1.f - g) * sp[t], 0.f);
    }
}

// ---------------------------------------------------------------------------
extern "C" void kernel_launch(void* const* d_in, const int* in_sizes, int n_in,
                              void* d_out, int out_size) {
    const float* h    = (const float*)d_in[0];
    const float* prev = (const float*)d_in[1];
    const float* emb  = (const float*)d_in[2];
    const float* norm = (const float*)d_in[3];
    const float* Wn   = (const float*)d_in[4];
    const float* Wl   = (const float*)d_in[5];
    const float* We   = (const float*)d_in[6];
    const float* Wsk  = (const float*)d_in[7];
    const float* bias = (const float*)d_in[8];
    const int* src = (const int*)d_in[9];     // int32 (JAX x64-disabled)
    const int* dst = (const int*)d_in[10];
    const int* et  = (const int*)d_in[11];
    int N = in_sizes[3];
    if (N > NMAX) N = NMAX;
    int E = in_sizes[9];
    float* out = (float*)d_out;

    void *pS, *pF, *pC;
    cudaGetSymbolAddress(&pS, g_S4);
    cudaGetSymbolAddress(&pF, g_flag);
    cudaGetSymbolAddress(&pC, g_cnt);
    cudaMemsetAsync(pS, 0, (size_t)N * D * sizeof(float), 0);
    cudaMemsetAsync(pF, 0, (size_t)N * sizeof(int), 0);
    cudaMemsetAsync(pC, 0, sizeof(int), 0);

    wtrans<<<192, 256>>>(Wn, Wl, Wsk);

    int edgeBlocks = (E + 7) / 8;
    edge_kernel<<<edgeBlocks, 256>>>(h, emb, src, dst, et, E);

    build_list<<<(N + 255) / 256, 256>>>(N);

    cudaFuncSetAttribute(node_wmma,
                         cudaFuncAttributeMaxDynamicSharedMemorySize, SM_TOT);
    node_wmma<<<(N + 127) / 128, 512, SM_TOT>>>(h, prev, norm, bias, out, N);

    fix_kernel<<<2048, 128>>>(h, prev, We, Wsk, bias, out);
}